// round 1
// baseline (speedup 1.0000x reference)
#include <cuda_runtime.h>

#define BB   4
#define NN   2048
#define DD   1024
#define EE   8
#define BT   128
#define NTOK (BB*NN)
#define ATT_SCALE 0.08838834764831845f  /* 1/sqrt(128) */

// ---------------- scratch (device globals; no allocs allowed) ----------------
__device__ int   g_topi[NTOK*2];
__device__ float g_topw[NTOK*2];
__device__ float g_psum[EE];
__device__ int   g_counts[BB*EE];
__device__ int   g_idx[BB*EE*NN];
__device__ float g_q[(size_t)BB*EE*NN*BT];
__device__ float g_k[(size_t)BB*EE*NN*BT];
__device__ float g_v[(size_t)BB*EE*NN*BT];
__device__ float g_c[(size_t)BB*EE*NN*BT];
__device__ float g_ys[(size_t)NTOK*2*DD];

// ---------------- K0: zero accumulators (graph-replay determinism) ----------
__global__ void k_zero() {
    if (threadIdx.x < EE) g_psum[threadIdx.x] = 0.f;
}

// ---------------- K1: router: logits, softmax, top-2, prob sums -------------
__global__ void k_router(const float* __restrict__ x, const float* __restrict__ wg) {
    int warp = threadIdx.x >> 5, lane = threadIdx.x & 31;
    int tok = blockIdx.x * 8 + warp;                // 8 tokens per 256-thread block
    const float* xr = x + (size_t)tok * DD;
    float acc[EE];
#pragma unroll
    for (int e = 0; e < EE; e++) acc[e] = 0.f;
    for (int d = lane; d < DD; d += 32) {
        float xv = xr[d];
        float4 w0 = *(const float4*)(wg + d * EE);
        float4 w1 = *(const float4*)(wg + d * EE + 4);
        acc[0] += xv * w0.x; acc[1] += xv * w0.y; acc[2] += xv * w0.z; acc[3] += xv * w0.w;
        acc[4] += xv * w1.x; acc[5] += xv * w1.y; acc[6] += xv * w1.z; acc[7] += xv * w1.w;
    }
#pragma unroll
    for (int o = 16; o > 0; o >>= 1)
#pragma unroll
        for (int e = 0; e < EE; e++) acc[e] += __shfl_down_sync(0xffffffffu, acc[e], o);
    if (lane == 0) {
        float m = acc[0];
#pragma unroll
        for (int e = 1; e < EE; e++) m = fmaxf(m, acc[e]);
        float p[EE]; float s = 0.f;
#pragma unroll
        for (int e = 0; e < EE; e++) { p[e] = __expf(acc[e] - m); s += p[e]; }
        float inv = 1.f / s;
#pragma unroll
        for (int e = 0; e < EE; e++) p[e] *= inv;
        int i1 = 0;
#pragma unroll
        for (int e = 1; e < EE; e++) if (p[e] > p[i1]) i1 = e;
        int i2 = (i1 == 0) ? 1 : 0;
#pragma unroll
        for (int e = 0; e < EE; e++) if (e != i1 && p[e] > p[i2]) i2 = e;
        float ws = p[i1] + p[i2];
        g_topi[tok*2+0] = i1; g_topi[tok*2+1] = i2;
        g_topw[tok*2+0] = p[i1] / ws; g_topw[tok*2+1] = p[i2] / ws;
#pragma unroll
        for (int e = 0; e < EE; e++) atomicAdd(&g_psum[e], p[e]);
    }
}

// ---------------- K2: order-preserving compaction per (b,e) -----------------
__global__ void k_compact() {
    int be = blockIdx.x; int b = be >> 3, e = be & 7;
    __shared__ int s_base, s_wcnt[8];
    int tid = threadIdx.x, lane = tid & 31, wid = tid >> 5;
    if (tid == 0) s_base = 0;
    __syncthreads();
    for (int base = 0; base < NN; base += 256) {
        int n = base + tid;
        bool flag = (g_topi[(b*NN+n)*2] == e) || (g_topi[(b*NN+n)*2+1] == e);
        unsigned bal = __ballot_sync(0xffffffffu, flag);
        if (lane == 0) s_wcnt[wid] = __popc(bal);
        __syncthreads();
        int off = s_base;
        for (int w = 0; w < wid; w++) off += s_wcnt[w];
        off += __popc(bal & ((1u << lane) - 1));
        if (flag) g_idx[be*NN + off] = n;
        int tot = 0;
        for (int w = 0; w < 8; w++) tot += s_wcnt[w];
        __syncthreads();
        if (tid == 0) s_base += tot;
        __syncthreads();
    }
    if (tid == 0) g_counts[be] = s_base;
}

// ---------------- K3: gathered h = x@Wd, then q/k/v = h@W ------------------
__global__ __launch_bounds__(256) void k_qkv(
        const float* __restrict__ x,  const float* __restrict__ Wd,
        const float* __restrict__ Wq, const float* __restrict__ Wk,
        const float* __restrict__ Wv) {
    int be = blockIdx.y, b = be >> 3, e = be & 7;
    int cnt = g_counts[be];
    int r0 = blockIdx.x * 32;
    if (r0 >= cnt) return;
    __shared__ float s_x[32*33];
    __shared__ float s_w[32*132];
    __shared__ float s_h[32*132];
    __shared__ int   s_tok[32];
    int tid = threadIdx.x;
    if (tid < 32) s_tok[tid] = (r0 + tid < cnt) ? g_idx[be*NN + r0 + tid] : 0;
    __syncthreads();
    int cg = tid & 31;            // 32 col-groups of 4 cols
    int rg = tid >> 5;            // 8 row-groups of 4 rows
    int col = cg * 4;
    float hacc[4][4];
#pragma unroll
    for (int rr = 0; rr < 4; rr++)
#pragma unroll
        for (int cc = 0; cc < 4; cc++) hacc[rr][cc] = 0.f;
    const float* wd_e = Wd + (size_t)e * DD * BT;
    for (int dc = 0; dc < DD; dc += 32) {
#pragma unroll
        for (int ii = 0; ii < 4; ii++) {
            int li = tid + ii * 256;
            int rr = li >> 5, dd2 = li & 31;
            s_x[rr*33 + dd2] = x[((size_t)b*NN + s_tok[rr]) * DD + dc + dd2];
        }
#pragma unroll
        for (int ii = 0; ii < 16; ii++) {
            int li = tid + ii * 256;
            int dd2 = li >> 7, c = li & 127;
            s_w[dd2*132 + c] = wd_e[(size_t)(dc + dd2) * BT + c];
        }
        __syncthreads();
#pragma unroll
        for (int kk = 0; kk < 32; kk++) {
            float4 wv = *(float4*)&s_w[kk*132 + col];
#pragma unroll
            for (int rr = 0; rr < 4; rr++) {
                float xv = s_x[(rg*4+rr)*33 + kk];
                hacc[rr][0] += xv * wv.x; hacc[rr][1] += xv * wv.y;
                hacc[rr][2] += xv * wv.z; hacc[rr][3] += xv * wv.w;
            }
        }
        __syncthreads();
    }
#pragma unroll
    for (int rr = 0; rr < 4; rr++)
        *(float4*)&s_h[(rg*4+rr)*132 + col] =
            make_float4(hacc[rr][0], hacc[rr][1], hacc[rr][2], hacc[rr][3]);
    __syncthreads();

    float qa[4][4], ka[4][4], va[4][4];
#pragma unroll
    for (int rr = 0; rr < 4; rr++)
#pragma unroll
        for (int cc = 0; cc < 4; cc++) { qa[rr][cc]=0.f; ka[rr][cc]=0.f; va[rr][cc]=0.f; }
    const float* wq_e = Wq + (size_t)e * BT * BT;
    const float* wk_e = Wk + (size_t)e * BT * BT;
    const float* wv_e = Wv + (size_t)e * BT * BT;
    for (int kk = 0; kk < BT; kk++) {
        float4 wq4 = *(const float4*)(wq_e + kk*BT + col);
        float4 wk4 = *(const float4*)(wk_e + kk*BT + col);
        float4 wv4 = *(const float4*)(wv_e + kk*BT + col);
#pragma unroll
        for (int rr = 0; rr < 4; rr++) {
            float hv = s_h[(rg*4+rr)*132 + kk];
            qa[rr][0]+=hv*wq4.x; qa[rr][1]+=hv*wq4.y; qa[rr][2]+=hv*wq4.z; qa[rr][3]+=hv*wq4.w;
            ka[rr][0]+=hv*wk4.x; ka[rr][1]+=hv*wk4.y; ka[rr][2]+=hv*wk4.z; ka[rr][3]+=hv*wk4.w;
            va[rr][0]+=hv*wv4.x; va[rr][1]+=hv*wv4.y; va[rr][2]+=hv*wv4.z; va[rr][3]+=hv*wv4.w;
        }
    }
    size_t base = ((size_t)be * NN + r0) * BT;
#pragma unroll
    for (int rr = 0; rr < 4; rr++) {
        size_t off = base + (size_t)(rg*4+rr) * BT + col;
        *(float4*)&g_q[off] = make_float4(qa[rr][0], qa[rr][1], qa[rr][2], qa[rr][3]);
        *(float4*)&g_k[off] = make_float4(ka[rr][0], ka[rr][1], ka[rr][2], ka[rr][3]);
        *(float4*)&g_v[off] = make_float4(va[rr][0], va[rr][1], va[rr][2], va[rr][3]);
    }
}

// ---------------- K4: flash attention over compacted tokens ----------------
__global__ __launch_bounds__(256) void k_attn() {
    extern __shared__ float sm[];
    float* q_s    = sm;                 // 64 x 132
    float* kT     = q_s + 64*132;       // 128 x 68 (transposed)
    float* v_s    = kT + 128*68;        // 64 x 132
    float* s_s    = v_s + 64*132;       // 64 x 68
    float* corr_s = s_s + 64*68;        // 64
    float* l_s    = corr_s + 64;        // 64

    int be = blockIdx.y;
    int cnt = g_counts[be];
    int qt = blockIdx.x;
    int qbase = qt * 64;
    if (qbase >= cnt) return;
    int tid = threadIdx.x;
    const float* qg = g_q + (size_t)be * NN * BT;
    const float* kg = g_k + (size_t)be * NN * BT;
    const float* vg = g_v + (size_t)be * NN * BT;
#pragma unroll
    for (int ii = 0; ii < 32; ii++) {
        int li = tid + ii * 256;
        int row = li >> 7, dd = li & 127;
        q_s[row*132 + dd] = qg[(size_t)(qbase + row) * BT + dd];
    }
    float m_i = -1e30f, l_i = 0.f;      // valid in tid<64 only
    float acc[32];
#pragma unroll
    for (int i = 0; i < 32; i++) acc[i] = 0.f;
    int tx = tid & 15, ty = tid >> 4;
    int ra = tid >> 2, chunk = tid & 3, c0 = chunk * 32;

    for (int kt = 0; kt <= qt; kt++) {
        int kbase = kt * 64;
        __syncthreads();   // previous tile fully consumed (also covers q_s fill)
#pragma unroll
        for (int ii = 0; ii < 32; ii++) {
            int li = tid + ii * 256;
            int row = li >> 7, dd = li & 127;
            bool ok = (kbase + row) < cnt;
            kT[dd*68 + row]  = ok ? kg[(size_t)(kbase + row) * BT + dd] : 0.f;
            v_s[row*132 + dd] = ok ? vg[(size_t)(kbase + row) * BT + dd] : 0.f;
        }
        __syncthreads();
        float sc[4][4];
#pragma unroll
        for (int i = 0; i < 4; i++)
#pragma unroll
            for (int j = 0; j < 4; j++) sc[i][j] = 0.f;
        for (int d = 0; d < 128; d++) {
            float4 kv = *(float4*)&kT[d*68 + tx*4];
#pragma unroll
            for (int ii = 0; ii < 4; ii++) {
                float qv = q_s[(ty*4+ii)*132 + d];
                sc[ii][0] += qv*kv.x; sc[ii][1] += qv*kv.y;
                sc[ii][2] += qv*kv.z; sc[ii][3] += qv*kv.w;
            }
        }
#pragma unroll
        for (int ii = 0; ii < 4; ii++)
#pragma unroll
            for (int jj = 0; jj < 4; jj++) {
                int qi = qbase + ty*4 + ii, kj = kbase + tx*4 + jj;
                s_s[(ty*4+ii)*68 + tx*4+jj] =
                    (kj <= qi && kj < cnt) ? sc[ii][jj] * ATT_SCALE : -1e30f;
            }
        __syncthreads();
        if (tid < 64) {
            float mloc = -1e30f;
            for (int j = 0; j < 64; j++) mloc = fmaxf(mloc, s_s[tid*68 + j]);
            float mnew = fmaxf(m_i, mloc);
            float corr = __expf(m_i - mnew);
            float ls = 0.f;
            for (int j = 0; j < 64; j++) {
                float p = __expf(s_s[tid*68 + j] - mnew);
                s_s[tid*68 + j] = p;
                ls += p;
            }
            l_i = l_i * corr + ls;
            m_i = mnew;
            corr_s[tid] = corr;
        }
        __syncthreads();
        float cf = corr_s[ra];
#pragma unroll
        for (int i = 0; i < 32; i++) acc[i] *= cf;
        for (int j = 0; j < 64; j++) {
            float p = s_s[ra*68 + j];
            const float* vr = &v_s[j*132 + c0];
#pragma unroll
            for (int i4 = 0; i4 < 8; i4++) {
                float4 vv = *(float4*)(vr + i4*4);
                acc[i4*4+0] += p*vv.x; acc[i4*4+1] += p*vv.y;
                acc[i4*4+2] += p*vv.z; acc[i4*4+3] += p*vv.w;
            }
        }
    }
    __syncthreads();
    if (tid < 64) l_s[tid] = l_i;
    __syncthreads();
    if (qbase + ra < cnt) {
        float invl = 1.f / l_s[ra];
        float* cgp = g_c + (size_t)be * NN * BT + (size_t)(qbase + ra) * BT + c0;
#pragma unroll
        for (int i4 = 0; i4 < 8; i4++) {
            *(float4*)(cgp + i4*4) = make_float4(acc[i4*4]*invl, acc[i4*4+1]*invl,
                                                 acc[i4*4+2]*invl, acc[i4*4+3]*invl);
        }
    }
}

// ---------------- K5: y = c @ W_up, weighted, scattered to (token,slot) ----
__global__ __launch_bounds__(256) void k_yup(const float* __restrict__ Wu) {
    int be = blockIdx.y, b = be >> 3, e = be & 7;
    int cnt = g_counts[be];
    int r0 = blockIdx.x * 32;
    if (r0 >= cnt) return;
    __shared__ float s_c[32*132];
    __shared__ int   s_tok[32];
    __shared__ int   s_j[32];
    __shared__ float s_wt[32];
    int tid = threadIdx.x;
    if (tid < 32) {
        bool valid = (r0 + tid) < cnt;
        int tok = valid ? g_idx[be*NN + r0 + tid] : 0;
        int gt = b*NN + tok;
        int j = (g_topi[gt*2] == e) ? 0 : 1;
        s_tok[tid] = tok; s_j[tid] = j;
        s_wt[tid] = valid ? g_topw[gt*2 + j] : 0.f;
    }
#pragma unroll
    for (int ii = 0; ii < 16; ii++) {
        int li = tid + ii * 256;
        int row = li >> 7, dd = li & 127;
        s_c[row*132 + dd] = g_c[(size_t)be*NN*BT + (size_t)(r0 + row)*BT + dd];
    }
    __syncthreads();
    const float* wu_e = Wu + (size_t)e * BT * DD;
    int col = tid * 4;                 // each thread owns 4 contiguous cols
    float a0[32], a1[32], a2[32], a3[32];
#pragma unroll
    for (int r = 0; r < 32; r++) { a0[r]=0.f; a1[r]=0.f; a2[r]=0.f; a3[r]=0.f; }
    for (int d = 0; d < BT; d++) {
        float4 w4 = *(const float4*)(wu_e + (size_t)d * DD + col);
#pragma unroll
        for (int r = 0; r < 32; r++) {
            float c = s_c[r*132 + d];
            a0[r] += c*w4.x; a1[r] += c*w4.y; a2[r] += c*w4.z; a3[r] += c*w4.w;
        }
    }
#pragma unroll 1
    for (int r = 0; r < 32; r++) {
        if (r0 + r < cnt) {
            float w = s_wt[r];
            size_t off = ((size_t)(b*NN + s_tok[r]) * 2 + s_j[r]) * DD + col;
            *(float4*)&g_ys[off] = make_float4(w*a0[r], w*a1[r], w*a2[r], w*a3[r]);
        }
    }
}

// ---------------- K6: combine the two expert outputs per token --------------
__global__ void k_combine(float* __restrict__ out) {
    size_t i = (size_t)blockIdx.x * 256 + threadIdx.x;   // float4 index
    size_t tokn = i >> 8;
    size_t c4 = i & 255;
    float4 a = ((const float4*)g_ys)[(tokn*2  )*256 + c4];
    float4 b = ((const float4*)g_ys)[(tokn*2+1)*256 + c4];
    ((float4*)out)[i] = make_float4(a.x+b.x, a.y+b.y, a.z+b.z, a.w+b.w);
}

// ---------------- K7: aux scalar outputs ------------------------------------
__global__ void k_loss(float* __restrict__ out) {
    if (threadIdx.x == 0) {
        float loss = 0.f, fmax = 0.f;
        float denom = (float)NTOK;
        for (int e = 0; e < EE; e++) {
            int c = 0;
            for (int b = 0; b < BB; b++) c += g_counts[b*EE + e];
            float frac = (float)c / denom;
            float pm = g_psum[e] / denom;
            loss += frac * pm;
            fmax = fmaxf(fmax, frac);
        }
        out[(size_t)NTOK * DD + 0] = ((float)EE / 2.0f) * loss;   // E/top_k = 4
        out[(size_t)NTOK * DD + 1] = fmax * ((float)EE / 2.0f) - 1.0f;
    }
}

// ---------------- launcher ---------------------------------------------------
extern "C" void kernel_launch(void* const* d_in, const int* in_sizes, int n_in,
                              void* d_out, int out_size) {
    const float* x  = (const float*)d_in[0];
    // d_in[1] position_ids (== arange), d_in[2] active_mask (== all true)
    const float* Wg = (const float*)d_in[3];
    const float* Wd = (const float*)d_in[4];
    const float* Wq = (const float*)d_in[5];
    const float* Wk = (const float*)d_in[6];
    const float* Wv = (const float*)d_in[7];
    const float* Wu = (const float*)d_in[8];
    float* out = (float*)d_out;

    static const int ATTN_SMEM = (64*132 + 128*68 + 64*132 + 64*68 + 128) * 4;
    cudaFuncSetAttribute(k_attn, cudaFuncAttributeMaxDynamicSharedMemorySize, ATTN_SMEM);

    k_zero<<<1, 32>>>();
    k_router<<<NTOK/8, 256>>>(x, Wg);
    k_compact<<<BB*EE, 256>>>();
    k_qkv<<<dim3(NN/32, BB*EE), 256>>>(x, Wd, Wq, Wk, Wv);
    k_attn<<<dim3(NN/64, BB*EE), 256, ATTN_SMEM>>>();
    k_yup<<<dim3(NN/32, BB*EE), 256>>>(Wu);
    k_combine<<<(NTOK*DD/4)/256, 256>>>(out);
    k_loss<<<1, 32>>>(out);
}

// round 2
// speedup vs baseline: 1.3826x; 1.3826x over previous
#include <cuda_runtime.h>

#define BB   4
#define NN   2048
#define DD   1024
#define EE   8
#define BT   128
#define NTOK (BB*NN)
#define ATT_SCALE 0.08838834764831845f  /* 1/sqrt(128) */

// ---------------- scratch (device globals; no allocs allowed) ----------------
__device__ int   g_topi[NTOK*2];
__device__ float g_topw[NTOK*2];
__device__ float g_psum[EE];
__device__ int   g_counts[BB*EE];
__device__ int   g_idx[BB*EE*NN];
__device__ float g_q[(size_t)BB*EE*NN*BT];
__device__ float g_k[(size_t)BB*EE*NN*BT];
__device__ float g_v[(size_t)BB*EE*NN*BT];
__device__ float g_c[(size_t)BB*EE*NN*BT];
__device__ float g_ys[(size_t)NTOK*2*DD];

// ---------------- K0: zero accumulators (graph-replay determinism) ----------
__global__ void k_zero() {
    if (threadIdx.x < EE) g_psum[threadIdx.x] = 0.f;
}

// ---------------- K1: router: logits, softmax, top-2, prob sums -------------
__global__ void k_router(const float* __restrict__ x, const float* __restrict__ wg) {
    __shared__ float s_p[EE];
    int tid = threadIdx.x;
    int warp = tid >> 5, lane = tid & 31;
    if (tid < EE) s_p[tid] = 0.f;
    __syncthreads();
    int tok = blockIdx.x * 8 + warp;                // 8 tokens per 256-thread block
    const float* xr = x + (size_t)tok * DD;
    float acc[EE];
#pragma unroll
    for (int e = 0; e < EE; e++) acc[e] = 0.f;
    for (int d = lane; d < DD; d += 32) {
        float xv = xr[d];
        float4 w0 = *(const float4*)(wg + d * EE);
        float4 w1 = *(const float4*)(wg + d * EE + 4);
        acc[0] += xv * w0.x; acc[1] += xv * w0.y; acc[2] += xv * w0.z; acc[3] += xv * w0.w;
        acc[4] += xv * w1.x; acc[5] += xv * w1.y; acc[6] += xv * w1.z; acc[7] += xv * w1.w;
    }
#pragma unroll
    for (int o = 16; o > 0; o >>= 1)
#pragma unroll
        for (int e = 0; e < EE; e++) acc[e] += __shfl_down_sync(0xffffffffu, acc[e], o);
    if (lane == 0) {
        float m = acc[0];
#pragma unroll
        for (int e = 1; e < EE; e++) m = fmaxf(m, acc[e]);
        float p[EE]; float s = 0.f;
#pragma unroll
        for (int e = 0; e < EE; e++) { p[e] = __expf(acc[e] - m); s += p[e]; }
        float inv = 1.f / s;
#pragma unroll
        for (int e = 0; e < EE; e++) p[e] *= inv;
        int i1 = 0;
#pragma unroll
        for (int e = 1; e < EE; e++) if (p[e] > p[i1]) i1 = e;
        int i2 = (i1 == 0) ? 1 : 0;
#pragma unroll
        for (int e = 0; e < EE; e++) if (e != i1 && p[e] > p[i2]) i2 = e;
        float ws = p[i1] + p[i2];
        g_topi[tok*2+0] = i1; g_topi[tok*2+1] = i2;
        g_topw[tok*2+0] = p[i1] / ws; g_topw[tok*2+1] = p[i2] / ws;
#pragma unroll
        for (int e = 0; e < EE; e++) atomicAdd(&s_p[e], p[e]);
    }
    __syncthreads();
    if (tid < EE) atomicAdd(&g_psum[tid], s_p[tid]);
}

// ---------------- K2: order-preserving compaction per (b,e) -----------------
__global__ void k_compact() {
    int be = blockIdx.x; int b = be >> 3, e = be & 7;
    __shared__ int s_base, s_wcnt[8];
    int tid = threadIdx.x, lane = tid & 31, wid = tid >> 5;
    if (tid == 0) s_base = 0;
    __syncthreads();
    for (int base = 0; base < NN; base += 256) {
        int n = base + tid;
        bool flag = (g_topi[(b*NN+n)*2] == e) || (g_topi[(b*NN+n)*2+1] == e);
        unsigned bal = __ballot_sync(0xffffffffu, flag);
        if (lane == 0) s_wcnt[wid] = __popc(bal);
        __syncthreads();
        int off = s_base;
        for (int w = 0; w < wid; w++) off += s_wcnt[w];
        off += __popc(bal & ((1u << lane) - 1));
        if (flag) g_idx[be*NN + off] = n;
        int tot = 0;
        for (int w = 0; w < 8; w++) tot += s_wcnt[w];
        __syncthreads();
        if (tid == 0) s_base += tot;
        __syncthreads();
    }
    if (tid == 0) g_counts[be] = s_base;
}

// ---------------- K3: gathered h = x@Wd, then q/k/v = h@W ------------------
// 64-row tiles, 256 threads, 8x4 microtile.
__global__ __launch_bounds__(256, 2) void k_qkv(
        const float* __restrict__ x,  const float* __restrict__ Wd,
        const float* __restrict__ Wq, const float* __restrict__ Wk,
        const float* __restrict__ Wv) {
    int be = blockIdx.y, b = be >> 3, e = be & 7;
    int cnt = g_counts[be];
    int r0 = blockIdx.x * 64;
    if (r0 >= cnt) return;
    __shared__ float s_x[64*20];
    __shared__ float s_w[16*128];
    __shared__ float s_h[64*132];
    __shared__ int   s_tok[64];
    int tid = threadIdx.x;
    if (tid < 64) s_tok[tid] = (r0 + tid < cnt) ? g_idx[be*NN + r0 + tid] : 0;
    __syncthreads();
    int tx = tid & 31, ty = tid >> 5;      // 32 col-groups x 8 row-groups
    int col = tx * 4;
    int lrow = tid >> 2, lc4 = (tid & 3) * 4;   // for s_x loads

    float acc[8][4];
#pragma unroll
    for (int r = 0; r < 8; r++)
#pragma unroll
        for (int c = 0; c < 4; c++) acc[r][c] = 0.f;

    const float* wd_e = Wd + (size_t)e * DD * BT;
    const float* xrow = x + ((size_t)b*NN + s_tok[lrow]) * DD + lc4;
    for (int dc = 0; dc < DD; dc += 16) {
        // s_x: 64 rows x 16 cols, one float4 per thread
        *(float4*)&s_x[lrow*20 + lc4] = *(const float4*)(xrow + dc);
        // s_w: 16 x 128, two float4 per thread
#pragma unroll
        for (int k2 = 0; k2 < 2; k2++) {
            int j = tid + k2 * 256;
            int wr = j >> 5, wc = (j & 31) * 4;
            *(float4*)&s_w[wr*128 + wc] = *(const float4*)(wd_e + (size_t)(dc + wr)*BT + wc);
        }
        __syncthreads();
#pragma unroll
        for (int kk = 0; kk < 16; kk++) {
            float4 wv = *(float4*)&s_w[kk*128 + col];
#pragma unroll
            for (int r = 0; r < 8; r++) {
                float xv = s_x[(ty*8+r)*20 + kk];
                acc[r][0] += xv*wv.x; acc[r][1] += xv*wv.y;
                acc[r][2] += xv*wv.z; acc[r][3] += xv*wv.w;
            }
        }
        __syncthreads();
    }
#pragma unroll
    for (int r = 0; r < 8; r++)
        *(float4*)&s_h[(ty*8+r)*132 + col] =
            make_float4(acc[r][0], acc[r][1], acc[r][2], acc[r][3]);
    __syncthreads();

    // stage 2: q/k/v = h @ W, sequentially reusing acc
    size_t obase = ((size_t)be * NN + r0) * BT;
#pragma unroll 1
    for (int m = 0; m < 3; m++) {
        const float* w_e = (m == 0 ? Wq : (m == 1 ? Wk : Wv)) + (size_t)e * BT * BT;
        float* dst = (m == 0 ? g_q : (m == 1 ? g_k : g_v));
#pragma unroll
        for (int r = 0; r < 8; r++)
#pragma unroll
            for (int c = 0; c < 4; c++) acc[r][c] = 0.f;
#pragma unroll 1
        for (int dc = 0; dc < BT; dc += 16) {
#pragma unroll
            for (int k2 = 0; k2 < 2; k2++) {
                int j = tid + k2 * 256;
                int wr = j >> 5, wc = (j & 31) * 4;
                *(float4*)&s_w[wr*128 + wc] = *(const float4*)(w_e + (size_t)(dc + wr)*BT + wc);
            }
            __syncthreads();
#pragma unroll
            for (int kk = 0; kk < 16; kk++) {
                float4 wv = *(float4*)&s_w[kk*128 + col];
#pragma unroll
                for (int r = 0; r < 8; r++) {
                    float hv = s_h[(ty*8+r)*132 + dc + kk];
                    acc[r][0] += hv*wv.x; acc[r][1] += hv*wv.y;
                    acc[r][2] += hv*wv.z; acc[r][3] += hv*wv.w;
                }
            }
            __syncthreads();
        }
#pragma unroll
        for (int r = 0; r < 8; r++) {
            size_t off = obase + (size_t)(ty*8+r) * BT + col;
            *(float4*)&dst[off] = make_float4(acc[r][0], acc[r][1], acc[r][2], acc[r][3]);
        }
    }
}

// ---------------- K4: flash attention over compacted tokens ----------------
__global__ __launch_bounds__(256) void k_attn() {
    extern __shared__ float sm[];
    float* q_s = sm;                 // 64 x 132
    float* kT  = q_s + 64*132;       // 128 x 68 (transposed)
    float* v_s = kT + 128*68;        // 64 x 132
    float* s_s = v_s + 64*132;       // 64 x 68

    int be = blockIdx.y;
    int cnt = g_counts[be];
    int qt = blockIdx.x;
    int qbase = qt * 64;
    if (qbase >= cnt) return;
    int tid = threadIdx.x;
    const float* qg = g_q + (size_t)be * NN * BT;
    const float* kg = g_k + (size_t)be * NN * BT;
    const float* vg = g_v + (size_t)be * NN * BT;
#pragma unroll
    for (int ii = 0; ii < 32; ii++) {
        int li = tid + ii * 256;
        int row = li >> 7, dd = li & 127;
        q_s[row*132 + dd] = qg[(size_t)(qbase + row) * BT + dd];
    }
    float m_i = -1e30f, l_i = 0.f;
    float racc[32];
#pragma unroll
    for (int i = 0; i < 32; i++) racc[i] = 0.f;
    int tx = tid & 15, ty = tid >> 4;
    int ra = tid >> 2, ch = tid & 3, c0 = ch * 32, j0 = ch * 16;

    for (int kt = 0; kt <= qt; kt++) {
        int kbase = kt * 64;
        __syncthreads();   // previous tile fully consumed (also covers q_s fill)
#pragma unroll
        for (int ii = 0; ii < 32; ii++) {
            int li = tid + ii * 256;
            int row = li >> 7, dd = li & 127;
            bool ok = (kbase + row) < cnt;
            kT[dd*68 + row]   = ok ? kg[(size_t)(kbase + row) * BT + dd] : 0.f;
            v_s[row*132 + dd] = ok ? vg[(size_t)(kbase + row) * BT + dd] : 0.f;
        }
        __syncthreads();
        float sc[4][4];
#pragma unroll
        for (int i = 0; i < 4; i++)
#pragma unroll
            for (int j = 0; j < 4; j++) sc[i][j] = 0.f;
        for (int d = 0; d < 128; d++) {
            float4 kv = *(float4*)&kT[d*68 + tx*4];
#pragma unroll
            for (int ii = 0; ii < 4; ii++) {
                float qv = q_s[(ty*4+ii)*132 + d];
                sc[ii][0] += qv*kv.x; sc[ii][1] += qv*kv.y;
                sc[ii][2] += qv*kv.z; sc[ii][3] += qv*kv.w;
            }
        }
#pragma unroll
        for (int ii = 0; ii < 4; ii++)
#pragma unroll
            for (int jj = 0; jj < 4; jj++) {
                int qi = qbase + ty*4 + ii, kj = kbase + tx*4 + jj;
                s_s[(ty*4+ii)*68 + tx*4+jj] =
                    (kj <= qi && kj < cnt) ? sc[ii][jj] * ATT_SCALE : -1e30f;
            }
        __syncthreads();
        // distributed online softmax: 4 lanes per row, 16 cols each
        float mloc = -1e30f;
#pragma unroll
        for (int jj = 0; jj < 16; jj++) mloc = fmaxf(mloc, s_s[ra*68 + j0 + jj]);
        mloc = fmaxf(mloc, __shfl_xor_sync(0xffffffffu, mloc, 1));
        mloc = fmaxf(mloc, __shfl_xor_sync(0xffffffffu, mloc, 2));
        float mnew = fmaxf(m_i, mloc);
        float corr = __expf(m_i - mnew);
        float ls = 0.f;
#pragma unroll
        for (int jj = 0; jj < 16; jj++) {
            float p = __expf(s_s[ra*68 + j0 + jj] - mnew);
            s_s[ra*68 + j0 + jj] = p;
            ls += p;
        }
        ls += __shfl_xor_sync(0xffffffffu, ls, 1);
        ls += __shfl_xor_sync(0xffffffffu, ls, 2);
        l_i = l_i * corr + ls;
        m_i = mnew;
        __syncwarp();
#pragma unroll
        for (int i = 0; i < 32; i++) racc[i] *= corr;
        for (int j = 0; j < 64; j++) {
            float p = s_s[ra*68 + j];
            const float* vr = &v_s[j*132 + c0];
#pragma unroll
            for (int i4 = 0; i4 < 8; i4++) {
                float4 vv = *(float4*)(vr + i4*4);
                racc[i4*4+0] += p*vv.x; racc[i4*4+1] += p*vv.y;
                racc[i4*4+2] += p*vv.z; racc[i4*4+3] += p*vv.w;
            }
        }
    }
    if (qbase + ra < cnt) {
        float invl = 1.f / l_i;
        float* cgp = g_c + (size_t)be * NN * BT + (size_t)(qbase + ra) * BT + c0;
#pragma unroll
        for (int i4 = 0; i4 < 8; i4++) {
            *(float4*)(cgp + i4*4) = make_float4(racc[i4*4]*invl, racc[i4*4+1]*invl,
                                                 racc[i4*4+2]*invl, racc[i4*4+3]*invl);
        }
    }
}

// ---------------- K5: y = c @ W_up, weighted, scattered to (token,slot) ----
// 64 rows x 128 cols per block, 8x4 microtile, grid.y = 8 column chunks.
__global__ __launch_bounds__(256, 2) void k_yup(const float* __restrict__ Wu) {
    int be = blockIdx.z, b = be >> 3, e = be & 7;
    int cnt = g_counts[be];
    int r0 = blockIdx.x * 64;
    if (r0 >= cnt) return;
    int cc = blockIdx.y;               // column chunk (128 cols)
    __shared__ float s_c[64*132];
    __shared__ float s_w[16*128];
    __shared__ int   s_tok[64];
    __shared__ int   s_j[64];
    __shared__ float s_wt[64];
    int tid = threadIdx.x;
    if (tid < 64) {
        bool valid = (r0 + tid) < cnt;
        int tok = valid ? g_idx[be*NN + r0 + tid] : 0;
        int gt = b*NN + tok;
        int j = (g_topi[gt*2] == e) ? 0 : 1;
        s_tok[tid] = tok; s_j[tid] = j;
        s_wt[tid] = valid ? g_topw[gt*2 + j] : 0.f;
    }
    // load c tile: 64 x 128, 8 float4 per thread
#pragma unroll
    for (int k2 = 0; k2 < 8; k2++) {
        int j = tid + k2 * 256;
        int row = j >> 5, cg = (j & 31) * 4;
        *(float4*)&s_c[row*132 + cg] =
            *(const float4*)&g_c[((size_t)be*NN + r0 + row)*BT + cg];
    }
    __syncthreads();
    int tx = tid & 31, ty = tid >> 5;
    int col = tx * 4;
    const float* wu_e = Wu + (size_t)e * BT * DD + cc * 128;
    float acc[8][4];
#pragma unroll
    for (int r = 0; r < 8; r++)
#pragma unroll
        for (int c = 0; c < 4; c++) acc[r][c] = 0.f;
#pragma unroll 1
    for (int dc = 0; dc < BT; dc += 16) {
#pragma unroll
        for (int k2 = 0; k2 < 2; k2++) {
            int j = tid + k2 * 256;
            int wr = j >> 5, wc = (j & 31) * 4;
            *(float4*)&s_w[wr*128 + wc] = *(const float4*)(wu_e + (size_t)(dc + wr)*DD + wc);
        }
        __syncthreads();
#pragma unroll
        for (int kk = 0; kk < 16; kk++) {
            float4 wv = *(float4*)&s_w[kk*128 + col];
#pragma unroll
            for (int r = 0; r < 8; r++) {
                float cv = s_c[(ty*8+r)*132 + dc + kk];
                acc[r][0] += cv*wv.x; acc[r][1] += cv*wv.y;
                acc[r][2] += cv*wv.z; acc[r][3] += cv*wv.w;
            }
        }
        __syncthreads();
    }
#pragma unroll
    for (int r = 0; r < 8; r++) {
        int row = ty*8 + r;
        if (r0 + row < cnt) {
            float w = s_wt[row];
            size_t off = ((size_t)(b*NN + s_tok[row]) * 2 + s_j[row]) * DD + cc * 128 + col;
            *(float4*)&g_ys[off] = make_float4(w*acc[r][0], w*acc[r][1],
                                               w*acc[r][2], w*acc[r][3]);
        }
    }
}

// ---------------- K6: combine the two expert outputs per token --------------
__global__ void k_combine(float* __restrict__ out) {
    size_t i = (size_t)blockIdx.x * 256 + threadIdx.x;   // float4 index
    size_t tokn = i >> 8;
    size_t c4 = i & 255;
    float4 a = ((const float4*)g_ys)[(tokn*2  )*256 + c4];
    float4 b = ((const float4*)g_ys)[(tokn*2+1)*256 + c4];
    ((float4*)out)[i] = make_float4(a.x+b.x, a.y+b.y, a.z+b.z, a.w+b.w);
}

// ---------------- K7: aux scalar outputs ------------------------------------
__global__ void k_loss(float* __restrict__ out) {
    if (threadIdx.x == 0) {
        float loss = 0.f, fmax = 0.f;
        float denom = (float)NTOK;
        for (int e = 0; e < EE; e++) {
            int c = 0;
            for (int b = 0; b < BB; b++) c += g_counts[b*EE + e];
            float frac = (float)c / denom;
            float pm = g_psum[e] / denom;
            loss += frac * pm;
            fmax = fmaxf(fmax, frac);
        }
        out[(size_t)NTOK * DD + 0] = ((float)EE / 2.0f) * loss;   // E/top_k = 4
        out[(size_t)NTOK * DD + 1] = fmax * ((float)EE / 2.0f) - 1.0f;
    }
}

// ---------------- launcher ---------------------------------------------------
extern "C" void kernel_launch(void* const* d_in, const int* in_sizes, int n_in,
                              void* d_out, int out_size) {
    const float* x  = (const float*)d_in[0];
    // d_in[1] position_ids (== arange), d_in[2] active_mask (== all true)
    const float* Wg = (const float*)d_in[3];
    const float* Wd = (const float*)d_in[4];
    const float* Wq = (const float*)d_in[5];
    const float* Wk = (const float*)d_in[6];
    const float* Wv = (const float*)d_in[7];
    const float* Wu = (const float*)d_in[8];
    float* out = (float*)d_out;

    static const int ATTN_SMEM = (64*132 + 128*68 + 64*132 + 64*68) * 4;
    cudaFuncSetAttribute(k_attn, cudaFuncAttributeMaxDynamicSharedMemorySize, ATTN_SMEM);

    k_zero<<<1, 32>>>();
    k_router<<<NTOK/8, 256>>>(x, Wg);
    k_compact<<<BB*EE, 256>>>();
    k_qkv<<<dim3(NN/64, BB*EE), 256>>>(x, Wd, Wq, Wk, Wv);
    k_attn<<<dim3(NN/64, BB*EE), 256, ATTN_SMEM>>>();
    k_yup<<<dim3(NN/64, 8, BB*EE), 256>>>(Wu);
    k_combine<<<(NTOK*DD/4)/256, 256>>>(out);
    k_loss<<<1, 32>>>(out);
}

// round 6
// speedup vs baseline: 1.4967x; 1.0825x over previous
#include <cuda_runtime.h>
#include <cuda_bf16.h>
#include <cstdint>

#define BB   4
#define NN   2048
#define DD   1024
#define EE   8
#define BT   128
#define NTOK (BB*NN)
#define ATT_SCALE 0.08838834764831845f  /* 1/sqrt(128) */

// ---------------- scratch (device globals; no allocs allowed) ----------------
__device__ int   g_topi[NTOK*2];
__device__ float g_topw[NTOK*2];
__device__ float g_psum[EE];
__device__ int   g_counts[BB*EE];
__device__ int   g_idx[BB*EE*NN];
__device__ float g_q[(size_t)BB*EE*NN*BT];
__device__ float g_k[(size_t)BB*EE*NN*BT];
__device__ float g_v[(size_t)BB*EE*NN*BT];
__device__ float g_c[(size_t)BB*EE*NN*BT];
__device__ float g_ys[(size_t)NTOK*2*DD];
// bf16 hi/lo split copies (bf16x3 emulated-fp32 MMA operands)
__device__ __nv_bfloat16 g_xhi[(size_t)NTOK*DD];
__device__ __nv_bfloat16 g_xlo[(size_t)NTOK*DD];
__device__ __nv_bfloat16 g_WdThi[EE*BT*DD];   // [e][c][d]  (n-major, k contiguous)
__device__ __nv_bfloat16 g_WdTlo[EE*BT*DD];
__device__ __nv_bfloat16 g_WqThi[EE*BT*BT];   // [e][out][in]
__device__ __nv_bfloat16 g_WqTlo[EE*BT*BT];
__device__ __nv_bfloat16 g_WkThi[EE*BT*BT];
__device__ __nv_bfloat16 g_WkTlo[EE*BT*BT];
__device__ __nv_bfloat16 g_WvThi[EE*BT*BT];
__device__ __nv_bfloat16 g_WvTlo[EE*BT*BT];
__device__ __nv_bfloat16 g_WuThi[EE*DD*BT];   // [e][n][k]
__device__ __nv_bfloat16 g_WuTlo[EE*DD*BT];

// ---------------- warp MMA helper: m16n8k16 bf16, fp32 acc ------------------
__device__ __forceinline__ void mma16816(float* d, const uint32_t* a, const uint32_t* b) {
    asm volatile("mma.sync.aligned.m16n8k16.row.col.f32.bf16.bf16.f32 "
        "{%0,%1,%2,%3}, {%4,%5,%6,%7}, {%8,%9}, {%0,%1,%2,%3};"
        : "+f"(d[0]), "+f"(d[1]), "+f"(d[2]), "+f"(d[3])
        : "r"(a[0]), "r"(a[1]), "r"(a[2]), "r"(a[3]), "r"(b[0]), "r"(b[1]));
}

__device__ __forceinline__ uint32_t pack2(float v0, float v1, uint32_t& lo_out) {
    __nv_bfloat16 h0 = __float2bfloat16(v0), h1 = __float2bfloat16(v1);
    __nv_bfloat16 l0 = __float2bfloat16(v0 - __bfloat162float(h0));
    __nv_bfloat16 l1 = __float2bfloat16(v1 - __bfloat162float(h1));
    lo_out = (uint32_t)__bfloat16_as_ushort(l0) | ((uint32_t)__bfloat16_as_ushort(l1) << 16);
    return (uint32_t)__bfloat16_as_ushort(h0) | ((uint32_t)__bfloat16_as_ushort(h1) << 16);
}

// ---------------- K0: zero accumulators -------------------------------------
__global__ void k_zero() {
    if (threadIdx.x < EE) g_psum[threadIdx.x] = 0.f;
}

// ---------------- prep: fp32 -> bf16 hi/lo (+ transposes) -------------------
__global__ void k_prep_x(const float* __restrict__ x) {
    size_t i = ((size_t)blockIdx.x * 256 + threadIdx.x) * 4;
    float4 v = *(const float4*)(x + i);
    uint32_t l01, l23;
    uint32_t h01 = pack2(v.x, v.y, l01);
    uint32_t h23 = pack2(v.z, v.w, l23);
    *(uint2*)(g_xhi + i) = make_uint2(h01, h23);
    *(uint2*)(g_xlo + i) = make_uint2(l01, l23);
}
__global__ void k_prep_wd(const float* __restrict__ Wd) {   // [e][d][c] -> [e][c][d]
    size_t gi = (size_t)blockIdx.x * 256 + threadIdx.x;
    int e = (int)(gi >> 17), r = (int)(gi & 131071);
    int d = r >> 7, c = r & 127;
    float v = Wd[gi];
    __nv_bfloat16 h = __float2bfloat16(v);
    __nv_bfloat16 l = __float2bfloat16(v - __bfloat162float(h));
    size_t o = ((size_t)e * BT + c) * DD + d;
    g_WdThi[o] = h; g_WdTlo[o] = l;
}
__global__ void k_prep_wqkv(const float* __restrict__ Wq, const float* __restrict__ Wk,
                            const float* __restrict__ Wv) {
    size_t gi = (size_t)blockIdx.x * 256 + threadIdx.x;
    int e = (int)(gi >> 14), r = (int)(gi & 16383);
    int t = r >> 7, c = r & 127;
    size_t o = ((size_t)e * BT + c) * BT + t;
    float v; __nv_bfloat16 h;
    v = Wq[gi]; h = __float2bfloat16(v);
    g_WqThi[o] = h; g_WqTlo[o] = __float2bfloat16(v - __bfloat162float(h));
    v = Wk[gi]; h = __float2bfloat16(v);
    g_WkThi[o] = h; g_WkTlo[o] = __float2bfloat16(v - __bfloat162float(h));
    v = Wv[gi]; h = __float2bfloat16(v);
    g_WvThi[o] = h; g_WvTlo[o] = __float2bfloat16(v - __bfloat162float(h));
}
__global__ void k_prep_wu(const float* __restrict__ Wu) {   // [e][t][n] -> [e][n][t]
    size_t gi = (size_t)blockIdx.x * 256 + threadIdx.x;
    int e = (int)(gi >> 17), r = (int)(gi & 131071);
    int t = r >> 10, n = r & 1023;
    float v = Wu[gi];
    __nv_bfloat16 h = __float2bfloat16(v);
    __nv_bfloat16 l = __float2bfloat16(v - __bfloat162float(h));
    size_t o = ((size_t)e * DD + n) * BT + t;
    g_WuThi[o] = h; g_WuTlo[o] = l;
}

// ---------------- K1: router ------------------------------------------------
__global__ void k_router(const float* __restrict__ x, const float* __restrict__ wg) {
    __shared__ float s_p[EE];
    int tid = threadIdx.x;
    int warp = tid >> 5, lane = tid & 31;
    if (tid < EE) s_p[tid] = 0.f;
    __syncthreads();
    int tok = blockIdx.x * 8 + warp;
    const float* xr = x + (size_t)tok * DD;
    float acc[EE];
#pragma unroll
    for (int e = 0; e < EE; e++) acc[e] = 0.f;
    for (int d = lane; d < DD; d += 32) {
        float xv = xr[d];
        float4 w0 = *(const float4*)(wg + d * EE);
        float4 w1 = *(const float4*)(wg + d * EE + 4);
        acc[0] += xv * w0.x; acc[1] += xv * w0.y; acc[2] += xv * w0.z; acc[3] += xv * w0.w;
        acc[4] += xv * w1.x; acc[5] += xv * w1.y; acc[6] += xv * w1.z; acc[7] += xv * w1.w;
    }
#pragma unroll
    for (int o = 16; o > 0; o >>= 1)
#pragma unroll
        for (int e = 0; e < EE; e++) acc[e] += __shfl_down_sync(0xffffffffu, acc[e], o);
    if (lane == 0) {
        float m = acc[0];
#pragma unroll
        for (int e = 1; e < EE; e++) m = fmaxf(m, acc[e]);
        float p[EE]; float s = 0.f;
#pragma unroll
        for (int e = 0; e < EE; e++) { p[e] = __expf(acc[e] - m); s += p[e]; }
        float inv = 1.f / s;
#pragma unroll
        for (int e = 0; e < EE; e++) p[e] *= inv;
        int i1 = 0;
#pragma unroll
        for (int e = 1; e < EE; e++) if (p[e] > p[i1]) i1 = e;
        int i2 = (i1 == 0) ? 1 : 0;
#pragma unroll
        for (int e = 0; e < EE; e++) if (e != i1 && p[e] > p[i2]) i2 = e;
        float ws = p[i1] + p[i2];
        g_topi[tok*2+0] = i1; g_topi[tok*2+1] = i2;
        g_topw[tok*2+0] = p[i1] / ws; g_topw[tok*2+1] = p[i2] / ws;
#pragma unroll
        for (int e = 0; e < EE; e++) atomicAdd(&s_p[e], p[e]);
    }
    __syncthreads();
    if (tid < EE) atomicAdd(&g_psum[tid], s_p[tid]);
}

// ---------------- K2: order-preserving compaction per (b,e) -----------------
__global__ void k_compact() {
    int be = blockIdx.x; int b = be >> 3, e = be & 7;
    __shared__ int s_base, s_wcnt[8];
    int tid = threadIdx.x, lane = tid & 31, wid = tid >> 5;
    if (tid == 0) s_base = 0;
    __syncthreads();
    for (int base = 0; base < NN; base += 256) {
        int n = base + tid;
        bool flag = (g_topi[(b*NN+n)*2] == e) || (g_topi[(b*NN+n)*2+1] == e);
        unsigned bal = __ballot_sync(0xffffffffu, flag);
        if (lane == 0) s_wcnt[wid] = __popc(bal);
        __syncthreads();
        int off = s_base;
        for (int w = 0; w < wid; w++) off += s_wcnt[w];
        off += __popc(bal & ((1u << lane) - 1));
        if (flag) g_idx[be*NN + off] = n;
        int tot = 0;
        for (int w = 0; w < 8; w++) tot += s_wcnt[w];
        __syncthreads();
        if (tid == 0) s_base += tot;
        __syncthreads();
    }
    if (tid == 0) g_counts[be] = s_base;
}

// ---------------- K3: HMMA bf16x3 fused h + q/k/v ---------------------------
// 128-token tiles, 256 threads (8 warps). A/B staged in smem as hi/lo bf16,
// K-chunks of 64. Strides: 72 b16 (A/B stage), 136 b16 (H) — conflict-free.
#define SAB   72
#define SH    136
#define OFF_AH 0
#define OFF_AL (OFF_AH + 128*SAB*2)
#define OFF_BH (OFF_AL + 128*SAB*2)
#define OFF_BL (OFF_BH + 128*SAB*2)
#define OFF_HH (OFF_BL + 128*SAB*2)
#define OFF_HL (OFF_HH + 128*SH*2)
#define QKV_SMEM (OFF_HL + 128*SH*2)

__global__ __launch_bounds__(256, 1) void k_qkv_hmma() {
    extern __shared__ __align__(16) char smem[];
    __nv_bfloat16* s_ah = (__nv_bfloat16*)(smem + OFF_AH);
    __nv_bfloat16* s_al = (__nv_bfloat16*)(smem + OFF_AL);
    __nv_bfloat16* s_bh = (__nv_bfloat16*)(smem + OFF_BH);
    __nv_bfloat16* s_bl = (__nv_bfloat16*)(smem + OFF_BL);
    __nv_bfloat16* s_hh = (__nv_bfloat16*)(smem + OFF_HH);
    __nv_bfloat16* s_hl = (__nv_bfloat16*)(smem + OFF_HL);
    __shared__ int s_tok[128];

    int be = blockIdx.y, b = be >> 3, e = be & 7;
    int cnt = g_counts[be];
    int r0 = blockIdx.x * 128;
    if (r0 >= cnt) return;
    int tid = threadIdx.x, w = tid >> 5, lane = tid & 31;
    int g = lane >> 2, t = lane & 3;
    int arow = w * 16 + g;
    if (tid < 128) s_tok[tid] = (r0 + tid < cnt) ? g_idx[be*NN + r0 + tid] : 0;
    __syncthreads();

    float acc[16][4];
#pragma unroll
    for (int nf = 0; nf < 16; nf++)
#pragma unroll
        for (int c = 0; c < 4; c++) acc[nf][c] = 0.f;

    // ---- stage 1: H = x @ Wd (K=1024, 16 chunks of 64) ----
    const __nv_bfloat16* wdh = g_WdThi + (size_t)e * BT * DD;
    const __nv_bfloat16* wdl = g_WdTlo + (size_t)e * BT * DD;
    for (int kc = 0; kc < DD; kc += 64) {
        __syncthreads();
#pragma unroll
        for (int i = 0; i < 4; i++) {
            int li = tid + i * 256;
            int row = li >> 3, q = li & 7;
            size_t ga = (size_t)(b*NN + s_tok[row]) * DD + kc + q * 8;
            *(uint4*)&s_ah[row*SAB + q*8] = *(const uint4*)(g_xhi + ga);
            *(uint4*)&s_al[row*SAB + q*8] = *(const uint4*)(g_xlo + ga);
            size_t gb = (size_t)row * DD + kc + q * 8;
            *(uint4*)&s_bh[row*SAB + q*8] = *(const uint4*)(wdh + gb);
            *(uint4*)&s_bl[row*SAB + q*8] = *(const uint4*)(wdl + gb);
        }
        __syncthreads();
#pragma unroll
        for (int kh = 0; kh < 4; kh++) {
            int k0 = kh * 16;
            uint32_t ah[4], al[4];
            ah[0] = *(uint32_t*)&s_ah[(arow  )*SAB + k0 + 2*t];
            ah[1] = *(uint32_t*)&s_ah[(arow+8)*SAB + k0 + 2*t];
            ah[2] = *(uint32_t*)&s_ah[(arow  )*SAB + k0 + 2*t + 8];
            ah[3] = *(uint32_t*)&s_ah[(arow+8)*SAB + k0 + 2*t + 8];
            al[0] = *(uint32_t*)&s_al[(arow  )*SAB + k0 + 2*t];
            al[1] = *(uint32_t*)&s_al[(arow+8)*SAB + k0 + 2*t];
            al[2] = *(uint32_t*)&s_al[(arow  )*SAB + k0 + 2*t + 8];
            al[3] = *(uint32_t*)&s_al[(arow+8)*SAB + k0 + 2*t + 8];
#pragma unroll
            for (int nf = 0; nf < 16; nf++) {
                int brow = nf * 8 + g;
                uint32_t bh[2], bl[2];
                bh[0] = *(uint32_t*)&s_bh[brow*SAB + k0 + 2*t];
                bh[1] = *(uint32_t*)&s_bh[brow*SAB + k0 + 2*t + 8];
                bl[0] = *(uint32_t*)&s_bl[brow*SAB + k0 + 2*t];
                bl[1] = *(uint32_t*)&s_bl[brow*SAB + k0 + 2*t + 8];
                mma16816(acc[nf], ah, bh);
                mma16816(acc[nf], ah, bl);
                mma16816(acc[nf], al, bh);
            }
        }
    }
    __syncthreads();
    // H -> smem hi/lo (fragment layout -> [row][k])
#pragma unroll
    for (int nf = 0; nf < 16; nf++) {
        uint32_t lo;
        uint32_t hi = pack2(acc[nf][0], acc[nf][1], lo);
        *(uint32_t*)&s_hh[(arow  )*SH + nf*8 + 2*t] = hi;
        *(uint32_t*)&s_hl[(arow  )*SH + nf*8 + 2*t] = lo;
        hi = pack2(acc[nf][2], acc[nf][3], lo);
        *(uint32_t*)&s_hh[(arow+8)*SH + nf*8 + 2*t] = hi;
        *(uint32_t*)&s_hl[(arow+8)*SH + nf*8 + 2*t] = lo;
    }
    __syncthreads();

    // ---- stage 2: q/k/v = H @ Wm (K=128, 2 chunks of 64 each) ----
    size_t obase = ((size_t)be * NN + r0) * BT;
#pragma unroll 1
    for (int m = 0; m < 3; m++) {
        const __nv_bfloat16* wh = (m == 0 ? g_WqThi : (m == 1 ? g_WkThi : g_WvThi)) + (size_t)e * BT * BT;
        const __nv_bfloat16* wl = (m == 0 ? g_WqTlo : (m == 1 ? g_WkTlo : g_WvTlo)) + (size_t)e * BT * BT;
#pragma unroll
        for (int nf = 0; nf < 16; nf++)
#pragma unroll
            for (int c = 0; c < 4; c++) acc[nf][c] = 0.f;
#pragma unroll 1
        for (int kc = 0; kc < BT; kc += 64) {
            __syncthreads();
#pragma unroll
            for (int i = 0; i < 4; i++) {
                int li = tid + i * 256;
                int row = li >> 3, q = li & 7;
                size_t gb = (size_t)row * BT + kc + q * 8;
                *(uint4*)&s_bh[row*SAB + q*8] = *(const uint4*)(wh + gb);
                *(uint4*)&s_bl[row*SAB + q*8] = *(const uint4*)(wl + gb);
            }
            __syncthreads();
#pragma unroll
            for (int kh = 0; kh < 4; kh++) {
                int k0 = kh * 16;
                int kg = kc + k0;
                uint32_t ah[4], al[4];
                ah[0] = *(uint32_t*)&s_hh[(arow  )*SH + kg + 2*t];
                ah[1] = *(uint32_t*)&s_hh[(arow+8)*SH + kg + 2*t];
                ah[2] = *(uint32_t*)&s_hh[(arow  )*SH + kg + 2*t + 8];
                ah[3] = *(uint32_t*)&s_hh[(arow+8)*SH + kg + 2*t + 8];
                al[0] = *(uint32_t*)&s_hl[(arow  )*SH + kg + 2*t];
                al[1] = *(uint32_t*)&s_hl[(arow+8)*SH + kg + 2*t];
                al[2] = *(uint32_t*)&s_hl[(arow  )*SH + kg + 2*t + 8];
                al[3] = *(uint32_t*)&s_hl[(arow+8)*SH + kg + 2*t + 8];
#pragma unroll
                for (int nf = 0; nf < 16; nf++) {
                    int brow = nf * 8 + g;
                    uint32_t bh[2], bl[2];
                    bh[0] = *(uint32_t*)&s_bh[brow*SAB + k0 + 2*t];
                    bh[1] = *(uint32_t*)&s_bh[brow*SAB + k0 + 2*t + 8];
                    bl[0] = *(uint32_t*)&s_bl[brow*SAB + k0 + 2*t];
                    bl[1] = *(uint32_t*)&s_bl[brow*SAB + k0 + 2*t + 8];
                    mma16816(acc[nf], ah, bh);
                    mma16816(acc[nf], ah, bl);
                    mma16816(acc[nf], al, bh);
                }
            }
        }
        float* dst = (m == 0 ? g_q : (m == 1 ? g_k : g_v));
#pragma unroll
        for (int nf = 0; nf < 16; nf++) {
            int col = nf * 8 + 2 * t;
            *(float2*)&dst[obase + (size_t)(arow  ) * BT + col] = make_float2(acc[nf][0], acc[nf][1]);
            *(float2*)&dst[obase + (size_t)(arow+8) * BT + col] = make_float2(acc[nf][2], acc[nf][3]);
        }
    }
}

// ---------------- K4: flash attention over compacted tokens (fp32) ----------
__global__ __launch_bounds__(256) void k_attn() {
    extern __shared__ float sm[];
    float* q_s = sm;                 // 64 x 132
    float* kT  = q_s + 64*132;       // 128 x 68 (transposed)
    float* v_s = kT + 128*68;        // 64 x 132
    float* s_s = v_s + 64*132;       // 64 x 68

    int be = blockIdx.y;
    int cnt = g_counts[be];
    int qt = blockIdx.x;
    int qbase = qt * 64;
    if (qbase >= cnt) return;
    int tid = threadIdx.x;
    const float* qg = g_q + (size_t)be * NN * BT;
    const float* kg = g_k + (size_t)be * NN * BT;
    const float* vg = g_v + (size_t)be * NN * BT;
#pragma unroll
    for (int ii = 0; ii < 32; ii++) {
        int li = tid + ii * 256;
        int row = li >> 7, dd = li & 127;
        q_s[row*132 + dd] = qg[(size_t)(qbase + row) * BT + dd];
    }
    float m_i = -1e30f, l_i = 0.f;
    float racc[32];
#pragma unroll
    for (int i = 0; i < 32; i++) racc[i] = 0.f;
    int tx = tid & 15, ty = tid >> 4;
    int ra = tid >> 2, ch = tid & 3, c0 = ch * 32, j0 = ch * 16;

    for (int kt = 0; kt <= qt; kt++) {
        int kbase = kt * 64;
        __syncthreads();
#pragma unroll
        for (int ii = 0; ii < 32; ii++) {
            int li = tid + ii * 256;
            int row = li >> 7, dd = li & 127;
            bool ok = (kbase + row) < cnt;
            kT[dd*68 + row]   = ok ? kg[(size_t)(kbase + row) * BT + dd] : 0.f;
            v_s[row*132 + dd] = ok ? vg[(size_t)(kbase + row) * BT + dd] : 0.f;
        }
        __syncthreads();
        float sc[4][4];
#pragma unroll
        for (int i = 0; i < 4; i++)
#pragma unroll
            for (int j = 0; j < 4; j++) sc[i][j] = 0.f;
        for (int d = 0; d < 128; d++) {
            float4 kv = *(float4*)&kT[d*68 + tx*4];
#pragma unroll
            for (int ii = 0; ii < 4; ii++) {
                float qv = q_s[(ty*4+ii)*132 + d];
                sc[ii][0] += qv*kv.x; sc[ii][1] += qv*kv.y;
                sc[ii][2] += qv*kv.z; sc[ii][3] += qv*kv.w;
            }
        }
#pragma unroll
        for (int ii = 0; ii < 4; ii++)
#pragma unroll
            for (int jj = 0; jj < 4; jj++) {
                int qi = qbase + ty*4 + ii, kj = kbase + tx*4 + jj;
                s_s[(ty*4+ii)*68 + tx*4+jj] =
                    (kj <= qi && kj < cnt) ? sc[ii][jj] * ATT_SCALE : -1e30f;
            }
        __syncthreads();
        float mloc = -1e30f;
#pragma unroll
        for (int jj = 0; jj < 16; jj++) mloc = fmaxf(mloc, s_s[ra*68 + j0 + jj]);
        mloc = fmaxf(mloc, __shfl_xor_sync(0xffffffffu, mloc, 1));
        mloc = fmaxf(mloc, __shfl_xor_sync(0xffffffffu, mloc, 2));
        float mnew = fmaxf(m_i, mloc);
        float corr = __expf(m_i - mnew);
        float ls = 0.f;
#pragma unroll
        for (int jj = 0; jj < 16; jj++) {
            float p = __expf(s_s[ra*68 + j0 + jj] - mnew);
            s_s[ra*68 + j0 + jj] = p;
            ls += p;
        }
        ls += __shfl_xor_sync(0xffffffffu, ls, 1);
        ls += __shfl_xor_sync(0xffffffffu, ls, 2);
        l_i = l_i * corr + ls;
        m_i = mnew;
        __syncwarp();
#pragma unroll
        for (int i = 0; i < 32; i++) racc[i] *= corr;
        for (int j = 0; j < 64; j++) {
            float p = s_s[ra*68 + j];
            const float* vr = &v_s[j*132 + c0];
#pragma unroll
            for (int i4 = 0; i4 < 8; i4++) {
                float4 vv = *(float4*)(vr + i4*4);
                racc[i4*4+0] += p*vv.x; racc[i4*4+1] += p*vv.y;
                racc[i4*4+2] += p*vv.z; racc[i4*4+3] += p*vv.w;
            }
        }
    }
    if (qbase + ra < cnt) {
        float invl = 1.f / l_i;
        float* cgp = g_c + (size_t)be * NN * BT + (size_t)(qbase + ra) * BT + c0;
#pragma unroll
        for (int i4 = 0; i4 < 8; i4++) {
            *(float4*)(cgp + i4*4) = make_float4(racc[i4*4]*invl, racc[i4*4+1]*invl,
                                                 racc[i4*4+2]*invl, racc[i4*4+3]*invl);
        }
    }
}

// ---------------- K5: HMMA bf16x3 y = c @ W_up ------------------------------
// 128 rows x 128 cols (col-block cb), K=128 in 2 chunks of 64.
#define YUP_SMEM (OFF_BL + 128*SAB*2)

__global__ __launch_bounds__(256, 1) void k_yup_hmma() {
    extern __shared__ __align__(16) char smem[];
    __nv_bfloat16* s_ah = (__nv_bfloat16*)(smem + OFF_AH);
    __nv_bfloat16* s_al = (__nv_bfloat16*)(smem + OFF_AL);
    __nv_bfloat16* s_bh = (__nv_bfloat16*)(smem + OFF_BH);
    __nv_bfloat16* s_bl = (__nv_bfloat16*)(smem + OFF_BL);
    __shared__ int   s_tok[128];
    __shared__ int   s_j[128];
    __shared__ float s_wt[128];

    int be = blockIdx.z, b = be >> 3, e = be & 7;
    int cnt = g_counts[be];
    int r0 = blockIdx.x * 128;
    if (r0 >= cnt) return;
    int cb = blockIdx.y;
    int tid = threadIdx.x, w = tid >> 5, lane = tid & 31;
    int g = lane >> 2, t = lane & 3;
    int arow = w * 16 + g;
    if (tid < 128) {
        bool valid = (r0 + tid) < cnt;
        int tok = valid ? g_idx[be*NN + r0 + tid] : 0;
        int gt = b*NN + tok;
        int j = (g_topi[gt*2] == e) ? 0 : 1;
        s_tok[tid] = tok; s_j[tid] = j;
        s_wt[tid] = valid ? g_topw[gt*2 + j] : 0.f;
    }
    __syncthreads();

    float acc[16][4];
#pragma unroll
    for (int nf = 0; nf < 16; nf++)
#pragma unroll
        for (int c = 0; c < 4; c++) acc[nf][c] = 0.f;

    const __nv_bfloat16* wh = g_WuThi + ((size_t)e * DD + cb * 128) * BT;
    const __nv_bfloat16* wl = g_WuTlo + ((size_t)e * DD + cb * 128) * BT;
#pragma unroll 1
    for (int kc = 0; kc < BT; kc += 64) {
        __syncthreads();
        // A: fp32 attention output -> hi/lo bf16
#pragma unroll
        for (int i = 0; i < 8; i++) {
            int li = tid + i * 256;
            int row = li >> 4, q = li & 15;           // 16 float4 per row of 64
            float4 v = *(const float4*)&g_c[((size_t)be*NN + r0 + row)*BT + kc + q*4];
            uint32_t l01, l23;
            uint32_t h01 = pack2(v.x, v.y, l01);
            uint32_t h23 = pack2(v.z, v.w, l23);
            *(uint2*)&s_ah[row*SAB + q*4] = make_uint2(h01, h23);
            *(uint2*)&s_al[row*SAB + q*4] = make_uint2(l01, l23);
        }
        // B: WuT rows
#pragma unroll
        for (int i = 0; i < 4; i++) {
            int li = tid + i * 256;
            int row = li >> 3, q = li & 7;
            size_t gb = (size_t)row * BT + kc + q * 8;
            *(uint4*)&s_bh[row*SAB + q*8] = *(const uint4*)(wh + gb);
            *(uint4*)&s_bl[row*SAB + q*8] = *(const uint4*)(wl + gb);
        }
        __syncthreads();
#pragma unroll
        for (int kh = 0; kh < 4; kh++) {
            int k0 = kh * 16;
            uint32_t ah[4], al[4];
            ah[0] = *(uint32_t*)&s_ah[(arow  )*SAB + k0 + 2*t];
            ah[1] = *(uint32_t*)&s_ah[(arow+8)*SAB + k0 + 2*t];
            ah[2] = *(uint32_t*)&s_ah[(arow  )*SAB + k0 + 2*t + 8];
            ah[3] = *(uint32_t*)&s_ah[(arow+8)*SAB + k0 + 2*t + 8];
            al[0] = *(uint32_t*)&s_al[(arow  )*SAB + k0 + 2*t];
            al[1] = *(uint32_t*)&s_al[(arow+8)*SAB + k0 + 2*t];
            al[2] = *(uint32_t*)&s_al[(arow  )*SAB + k0 + 2*t + 8];
            al[3] = *(uint32_t*)&s_al[(arow+8)*SAB + k0 + 2*t + 8];
#pragma unroll
            for (int nf = 0; nf < 16; nf++) {
                int brow = nf * 8 + g;
                uint32_t bh[2], bl[2];
                bh[0] = *(uint32_t*)&s_bh[brow*SAB + k0 + 2*t];
                bh[1] = *(uint32_t*)&s_bh[brow*SAB + k0 + 2*t + 8];
                bl[0] = *(uint32_t*)&s_bl[brow*SAB + k0 + 2*t];
                bl[1] = *(uint32_t*)&s_bl[brow*SAB + k0 + 2*t + 8];
                mma16816(acc[nf], ah, bh);
                mma16816(acc[nf], ah, bl);
                mma16816(acc[nf], al, bh);
            }
        }
    }
    // epilogue: weight + scatter to (token, slot)
    int rA = arow, rB = arow + 8;
    bool vA = (r0 + rA) < cnt, vB = (r0 + rB) < cnt;
    float wA = s_wt[rA], wB = s_wt[rB];
    size_t oA = (((size_t)(b*NN + s_tok[rA])) * 2 + s_j[rA]) * DD + cb * 128;
    size_t oB = (((size_t)(b*NN + s_tok[rB])) * 2 + s_j[rB]) * DD + cb * 128;
#pragma unroll
    for (int nf = 0; nf < 16; nf++) {
        int col = nf * 8 + 2 * t;
        if (vA) *(float2*)&g_ys[oA + col] = make_float2(wA*acc[nf][0], wA*acc[nf][1]);
        if (vB) *(float2*)&g_ys[oB + col] = make_float2(wB*acc[nf][2], wB*acc[nf][3]);
    }
}

// ---------------- K6: combine the two expert outputs per token --------------
__global__ void k_combine(float* __restrict__ out) {
    size_t i = (size_t)blockIdx.x * 256 + threadIdx.x;   // float4 index
    size_t tokn = i >> 8;
    size_t c4 = i & 255;
    float4 a = ((const float4*)g_ys)[(tokn*2  )*256 + c4];
    float4 b = ((const float4*)g_ys)[(tokn*2+1)*256 + c4];
    ((float4*)out)[i] = make_float4(a.x+b.x, a.y+b.y, a.z+b.z, a.w+b.w);
}

// ---------------- K7: aux scalar outputs ------------------------------------
__global__ void k_loss(float* __restrict__ out) {
    if (threadIdx.x == 0) {
        float loss = 0.f, fmax = 0.f;
        float denom = (float)NTOK;
        for (int e = 0; e < EE; e++) {
            int c = 0;
            for (int b = 0; b < BB; b++) c += g_counts[b*EE + e];
            float frac = (float)c / denom;
            float pm = g_psum[e] / denom;
            loss += frac * pm;
            fmax = fmaxf(fmax, frac);
        }
        out[(size_t)NTOK * DD + 0] = ((float)EE / 2.0f) * loss;
        out[(size_t)NTOK * DD + 1] = fmax * ((float)EE / 2.0f) - 1.0f;
    }
}

// ---------------- launcher ---------------------------------------------------
extern "C" void kernel_launch(void* const* d_in, const int* in_sizes, int n_in,
                              void* d_out, int out_size) {
    const float* x  = (const float*)d_in[0];
    const float* Wg = (const float*)d_in[3];
    const float* Wd = (const float*)d_in[4];
    const float* Wq = (const float*)d_in[5];
    const float* Wk = (const float*)d_in[6];
    const float* Wv = (const float*)d_in[7];
    const float* Wu = (const float*)d_in[8];
    float* out = (float*)d_out;

    static const int ATTN_SMEM = (64*132 + 128*68 + 64*132 + 64*68) * 4;
    cudaFuncSetAttribute(k_attn, cudaFuncAttributeMaxDynamicSharedMemorySize, ATTN_SMEM);
    cudaFuncSetAttribute(k_qkv_hmma, cudaFuncAttributeMaxDynamicSharedMemorySize, QKV_SMEM);
    cudaFuncSetAttribute(k_yup_hmma, cudaFuncAttributeMaxDynamicSharedMemorySize, YUP_SMEM);

    k_zero<<<1, 32>>>();
    k_prep_x<<<NTOK*DD/1024, 256>>>(x);
    k_prep_wd<<<EE*DD*BT/256, 256>>>(Wd);
    k_prep_wqkv<<<EE*BT*BT/256, 256>>>(Wq, Wk, Wv);
    k_prep_wu<<<EE*BT*DD/256, 256>>>(Wu);
    k_router<<<NTOK/8, 256>>>(x, Wg);
    k_compact<<<BB*EE, 256>>>();
    k_qkv_hmma<<<dim3(NN/128, BB*EE), 256, QKV_SMEM>>>();
    k_attn<<<dim3(NN/64, BB*EE), 256, ATTN_SMEM>>>();
    k_yup_hmma<<<dim3(NN/128, 8, BB*EE), 256, YUP_SMEM>>>();
    k_combine<<<(NTOK*DD/4)/256, 256>>>(out);
    k_loss<<<1, 32>>>(out);
}